// round 11
// baseline (speedup 1.0000x reference)
#include <cuda_runtime.h>
#include <cuda_bf16.h>

#define DEV_INLINE __device__ __forceinline__
constexpr int BATCH = 4;

// ---------------- buffer layout (floats) ----------------------------------
// NCHW padded: rows S+2, row-stride S+4. NHWC padded: [B][S+2][S+2][CST].
constexpr int OFF_X    = 0;                         // [4][3][34][36]
constexpr int SZ_X     = BATCH * 3 * 34 * 36;
constexpr int OFF_32A  = OFF_X + SZ_X;              // cap 64
constexpr int SZ_32    = BATCH * 64 * 34 * 36;
constexpr int OFF_32B  = OFF_32A + SZ_32;
constexpr int OFF_16A  = OFF_32B + SZ_32;           // cap 128
constexpr int SZ_16    = BATCH * 128 * 18 * 20;
constexpr int OFF_16B  = OFF_16A + SZ_16;
constexpr int OFF_8A   = OFF_16B + SZ_16;           // NHWC [4][10][10][256]
constexpr int SZ_8     = BATCH * 10 * 10 * 256;
constexpr int OFF_8B   = OFF_8A + SZ_8;
constexpr int OFF_4A   = OFF_8B + SZ_8;             // NHWC [4][6][6][512]
constexpr int SZ_4     = BATCH * 6 * 6 * 512;
constexpr int OFF_4B   = OFF_4A + SZ_4;
constexpr int OFF_2A   = OFF_4B + SZ_4;             // NHWC [4][4][4][512]
constexpr int SZ_2     = BATCH * 4 * 4 * 512;
constexpr int OFF_2B   = OFF_2A + SZ_2;
constexpr int OFF_FCS0 = OFF_2B + SZ_2;             // [4][4096]
constexpr int OFF_FCS1 = OFF_FCS0 + BATCH * 4096;

constexpr int M0  = OFF_FCS1 + BATCH * 4096;
constexpr int M1  = M0  + BATCH * 64  * 32 * 32;
constexpr int M2  = M1  + BATCH * 64  * 32 * 32;
constexpr int M3  = M2  + BATCH * 128 * 16 * 16;
constexpr int M4  = M3  + BATCH * 128 * 16 * 16;
constexpr int M5  = M4  + BATCH * 256 * 8 * 8;
constexpr int M6  = M5  + BATCH * 256 * 8 * 8;
constexpr int M7  = M6  + BATCH * 256 * 8 * 8;
constexpr int M8  = M7  + BATCH * 512 * 4 * 4;
constexpr int M9  = M8  + BATCH * 512 * 4 * 4;
constexpr int M10 = M9  + BATCH * 512 * 4 * 4;
constexpr int M11 = M10 + BATCH * 512 * 2 * 2;
constexpr int M12 = M11 + BATCH * 512 * 2 * 2;
constexpr int MF0 = M12 + BATCH * 512 * 2 * 2;
constexpr int MF1 = MF0 + BATCH * 4096;
constexpr int TOTAL_BUF = MF1 + BATCH * 4096;

__device__ __align__(16) float g_buf[TOTAL_BUF];

// transposed weights [co][tap][ci] for conv layers 4..12
constexpr long WT4  = 0;
constexpr long WT5  = WT4  + 256L * 128 * 9;
constexpr long WT6  = WT5  + 256L * 256 * 9;
constexpr long WT7  = WT6  + 256L * 256 * 9;
constexpr long WT8  = WT7  + 512L * 256 * 9;
constexpr long WT9  = WT8  + 512L * 512 * 9;
constexpr long WT10 = WT9  + 512L * 512 * 9;
constexpr long WT11 = WT10 + 512L * 512 * 9;
constexpr long WT12 = WT11 + 512L * 512 * 9;
constexpr long WT_TOTAL = WT12 + 512L * 512 * 9;
__device__ __align__(16) float g_wt[WT_TOTAL];

// ---------------- multi-compartment LIF (K=2), exact ----------------------
DEV_INLINE float lif_fire(float* memp, float syn, float thr, float leak) {
    float m = leak * (*memp) + syn;
    float e0 = m / thr          - 1.0f;
    float o0 = 1.0f - m / (2.0f * thr);
    float e1 = m / (2.0f * thr) - 1.0f;
    float o1 = 1.0f - m / (4.0f * thr);
    float v = 0.0f;
    if (e0 > 0.0f && o0 >= 0.0f) v = 1.0f;
    if (e1 > 0.0f && o1 >= 0.0f) v = 2.0f;
    *memp = m - thr * v;
    return v;
}

// ---------------- housekeeping --------------------------------------------
__global__ void k_zero(float* __restrict__ dout) {
    int i = blockIdx.x * blockDim.x + threadIdx.x;
    if (i < TOTAL_BUF) g_buf[i] = 0.0f;
    if (i < BATCH * 10) dout[i] = 0.0f;
}

__global__ void k_pad_x(const float* __restrict__ x) {
    int idx = blockIdx.x * blockDim.x + threadIdx.x;
    if (idx >= BATCH * 3 * 32 * 32) return;
    int xx = idx & 31;
    int y  = (idx >> 5) & 31;
    int c  = (idx >> 10) % 3;
    int b  = idx / (3 * 1024);
    g_buf[OFF_X + ((b * 3 + c) * 34 + (y + 1)) * 36 + (xx + 1)] = x[idx];
}

struct WP { const float* p[9]; };
__global__ void k_wtrans_all(WP wp) {
    __shared__ float s[4608];
    const int CINs[9]  = {128, 256, 256, 256, 512, 512, 512, 512, 512};
    const int COUTs[9] = {256, 256, 256, 512, 512, 512, 512, 512, 512};
    const long OFFs[9] = {WT4, WT5, WT6, WT7, WT8, WT9, WT10, WT11, WT12};
    int l  = blockIdx.y;
    int co = blockIdx.x;
    int CIN = CINs[l];
    if (co >= COUTs[l]) return;
    const float* src = wp.p[l] + (long)co * CIN * 9;
    float* dst = g_wt + OFFs[l] + (long)co * CIN * 9;
    int n = CIN * 9;
    for (int i = threadIdx.x; i < n; i += 256) s[i] = src[i];
    __syncthreads();
    for (int i = threadIdx.x; i < n; i += 256) {
        int ci = i % CIN, t = i / CIN;
        dst[i] = s[ci * 9 + t];
    }
}

// ---------------- conv flavor T: NCHW, TY=2 row blocking ------------------
// thread computes TX x 2 outputs; block = (co, part); weights in smem.
template<int CIN, int CICAP, int S, int COUT, int PARTS, int TX>
__global__ __launch_bounds__(256)
void k_conv_T(int in_off, const float* __restrict__ w, int mem_off, int out_off,
              const float* __restrict__ thrp, const float* __restrict__ leakp) {
    constexpr int RS = S + 4, ROWS = S + 2, NX = S / TX, NY = S / 2;
    constexpr int PLANE = ROWS * RS;
    constexpr int P = BATCH * NY * NX;
    constexpr int TPJ = P / PARTS;
    static_assert(TPJ == 256, "block must exactly cover its partition");
    constexpr int RC = (TX == 4) ? 8 : 4;   // resident cols per row
    __shared__ __align__(16) float sw[CIN * 12];
    int co   = blockIdx.x / PARTS;
    int part = blockIdx.x % PARTS;
    for (int i = threadIdx.x; i < CIN * 9; i += 256)
        sw[(i / 9) * 12 + (i % 9)] = __ldg(w + (long)co * CIN * 9 + i);
    __syncthreads();

    int tid = part * TPJ + threadIdx.x;
    int x0 = (tid % NX) * TX;
    int y0 = ((tid / NX) % NY) * 2;
    int b  = tid / (NX * NY);

    const float* ip = g_buf + in_off + (long)b * CICAP * PLANE + y0 * RS + x0;
    float acc[2][TX];
#pragma unroll
    for (int ty = 0; ty < 2; ty++)
#pragma unroll
        for (int t = 0; t < TX; t++) acc[ty][t] = 0.f;

    for (int ci = 0; ci < CIN; ci++) {
        const float* p = ip + ci * PLANE;
        float r[4][RC];
#pragma unroll
        for (int rr = 0; rr < 4; rr++) {
            if constexpr (TX == 4) {
                float4 a = __ldg((const float4*)(p + rr * RS));
                float4 c = __ldg((const float4*)(p + rr * RS + 4));
                r[rr][0] = a.x; r[rr][1] = a.y; r[rr][2] = a.z; r[rr][3] = a.w;
                r[rr][4] = c.x; r[rr][5] = c.y; r[rr][6] = c.z; r[rr][7] = c.w;
            } else {
                float2 a = __ldg((const float2*)(p + rr * RS));
                float2 c = __ldg((const float2*)(p + rr * RS + 2));
                r[rr][0] = a.x; r[rr][1] = a.y; r[rr][2] = c.x; r[rr][3] = c.y;
            }
        }
        float4 wa = *(const float4*)(sw + ci * 12);
        float4 wb = *(const float4*)(sw + ci * 12 + 4);
        float4 wc = *(const float4*)(sw + ci * 12 + 8);
        float wv[9] = {wa.x, wa.y, wa.z, wa.w, wb.x, wb.y, wb.z, wb.w, wc.x};
#pragma unroll
        for (int ty = 0; ty < 2; ty++)
#pragma unroll
            for (int t = 0; t < TX; t++)
                acc[ty][t] += wv[0]*r[ty][t]   + wv[1]*r[ty][t+1]   + wv[2]*r[ty][t+2]
                            + wv[3]*r[ty+1][t] + wv[4]*r[ty+1][t+1] + wv[5]*r[ty+1][t+2]
                            + wv[6]*r[ty+2][t] + wv[7]*r[ty+2][t+1] + wv[8]*r[ty+2][t+2];
    }

    float thr = __ldg(thrp), leak = __ldg(leakp);
#pragma unroll
    for (int ty = 0; ty < 2; ty++) {
        long mbase = (((long)b * COUT + co) * S + (y0 + ty)) * S + x0;
        long obase = (((long)b * COUT + co) * ROWS + (y0 + ty + 1)) * RS + (x0 + 1);
#pragma unroll
        for (int t = 0; t < TX; t++)
            g_buf[out_off + obase + t] =
                lif_fire(&g_buf[mem_off + mbase + t], acc[ty][t], thr, leak);
    }
}

// ---------------- conv flavor G: NHWC, warp=(b,y), G co's/warp (S=8) ------
template<int CIN, int CST, int S, int COUT, int G, int WPB, int PARTS>
__global__ __launch_bounds__(WPB * 32)
void k_conv_G(int in_off, long wt_off, int mem_off, int out_off,
              const float* __restrict__ thrp, const float* __restrict__ leakp) {
    constexpr int SP = S + 2;
    constexpr int NTHR = WPB * 32;
    constexpr int CHUNKS = CIN / 128;
    static_assert(WPB * PARTS == BATCH * S, "warps must exactly cover jobs");
    static_assert(G * S <= 32, "one lane per output");
    __shared__ __align__(16) float sw[G * 9 * 128];

    int cog  = blockIdx.x / PARTS;
    int part = blockIdx.x % PARTS;
    int warp = threadIdx.x >> 5, lane = threadIdx.x & 31;
    int job  = part * WPB + warp;
    int b = job / S, y = job % S;

    float acc[G][S];
#pragma unroll
    for (int g = 0; g < G; g++)
#pragma unroll
        for (int x = 0; x < S; x++) acc[g][x] = 0.f;

    int cb = lane * 4;
    for (int ch = 0; ch < CHUNKS; ch++) {
        __syncthreads();
        const float* wsrc = g_wt + wt_off + ((long)cog * G) * CIN * 9 + ch * 128;
        for (int i = threadIdx.x; i < G * 9 * 32; i += NTHR) {
            int g = i / (9 * 32);
            int r = i % (9 * 32);
            int t = r / 32, c4 = r % 32;
            *(float4*)(sw + (g * 9 + t) * 128 + c4 * 4) =
                __ldg((const float4*)(wsrc + ((long)g * 9 + t) * CIN + c4 * 4));
        }
        __syncthreads();

        const float* base = g_buf + in_off + ch * 128 + cb;
#pragma unroll
        for (int rr = 0; rr < 3; rr++) {
            const float* rp = base + ((long)(b * SP + y + rr) * SP) * CST;
            float4 a[S + 2];
#pragma unroll
            for (int j = 0; j < S + 2; j++)
                a[j] = __ldg((const float4*)(rp + (long)j * CST));
#pragma unroll
            for (int g = 0; g < G; g++) {
                const float* wrow = sw + (g * 9 + rr * 3) * 128 + cb;
                float4 w0 = *(const float4*)(wrow);
                float4 w1 = *(const float4*)(wrow + 128);
                float4 w2 = *(const float4*)(wrow + 256);
#pragma unroll
                for (int x = 0; x < S; x++) {
                    float4 a0 = a[x], a1 = a[x + 1], a2 = a[x + 2];
                    acc[g][x] += a0.x*w0.x + a0.y*w0.y + a0.z*w0.z + a0.w*w0.w
                               + a1.x*w1.x + a1.y*w1.y + a1.z*w1.z + a1.w*w1.w
                               + a2.x*w2.x + a2.y*w2.y + a2.z*w2.z + a2.w*w2.w;
                }
            }
        }
    }

    float mine = 0.f;
#pragma unroll
    for (int g = 0; g < G; g++)
#pragma unroll
        for (int x = 0; x < S; x++) {
            float v = acc[g][x];
#pragma unroll
            for (int o = 16; o; o >>= 1)
                v += __shfl_xor_sync(0xffffffffu, v, o);
            if (lane == g * S + x) mine = v;
        }

    if (lane < G * S) {
        int g = lane / S, x = lane % S;
        int co = cog * G + g;
        float thr = __ldg(thrp), leak = __ldg(leakp);
        long midx = (((long)b * S + y) * S + x) * COUT + co;
        long oidx = (((long)b * SP + (y + 1)) * SP + (x + 1)) * (long)COUT + co;
        g_buf[out_off + oidx] =
            lif_fire(&g_buf[mem_off + midx], mine, thr, leak);
    }
}

// ---------------- conv flavor GR: S<=4, all 3 rows register-resident ------
// Per 128-ci chunk: 3*(S+2) LDG.128 batched up front (full MLP), then pure
// FMA sweep over G co's with smem weights.
template<int CIN, int CST, int S, int COUT, int G, int WPB, int PARTS>
__global__ __launch_bounds__(WPB * 32)
void k_conv_GR(int in_off, long wt_off, int mem_off, int out_off,
               const float* __restrict__ thrp, const float* __restrict__ leakp) {
    constexpr int SP = S + 2;
    constexpr int NTHR = WPB * 32;
    constexpr int CHUNKS = CIN / 128;
    static_assert(WPB * PARTS == BATCH * S, "warps must exactly cover jobs");
    static_assert(G * S <= 32, "one lane per output");
    __shared__ __align__(16) float sw[G * 9 * 128];

    int cog  = blockIdx.x / PARTS;
    int part = blockIdx.x % PARTS;
    int warp = threadIdx.x >> 5, lane = threadIdx.x & 31;
    int job  = part * WPB + warp;
    int b = job / S, y = job % S;

    float acc[G][S];
#pragma unroll
    for (int g = 0; g < G; g++)
#pragma unroll
        for (int x = 0; x < S; x++) acc[g][x] = 0.f;

    int cb = lane * 4;
    for (int ch = 0; ch < CHUNKS; ch++) {
        __syncthreads();
        const float* wsrc = g_wt + wt_off + ((long)cog * G) * CIN * 9 + ch * 128;
        for (int i = threadIdx.x; i < G * 9 * 32; i += NTHR) {
            int g = i / (9 * 32);
            int r = i % (9 * 32);
            int t = r / 32, c4 = r % 32;
            *(float4*)(sw + (g * 9 + t) * 128 + c4 * 4) =
                __ldg((const float4*)(wsrc + ((long)g * 9 + t) * CIN + c4 * 4));
        }
        __syncthreads();

        // all 3*(S+2) activation vectors resident, loads fully batched
        const float* base = g_buf + in_off + ch * 128 + cb;
        float4 a[3][S + 2];
#pragma unroll
        for (int rr = 0; rr < 3; rr++) {
            const float* rp = base + ((long)(b * SP + y + rr) * SP) * CST;
#pragma unroll
            for (int j = 0; j < S + 2; j++)
                a[rr][j] = __ldg((const float4*)(rp + (long)j * CST));
        }
#pragma unroll
        for (int g = 0; g < G; g++) {
#pragma unroll
            for (int rr = 0; rr < 3; rr++) {
                const float* wrow = sw + (g * 9 + rr * 3) * 128 + cb;
                float4 w0 = *(const float4*)(wrow);
                float4 w1 = *(const float4*)(wrow + 128);
                float4 w2 = *(const float4*)(wrow + 256);
#pragma unroll
                for (int x = 0; x < S; x++) {
                    float4 a0 = a[rr][x], a1 = a[rr][x + 1], a2 = a[rr][x + 2];
                    acc[g][x] += a0.x*w0.x + a0.y*w0.y + a0.z*w0.z + a0.w*w0.w
                               + a1.x*w1.x + a1.y*w1.y + a1.z*w1.z + a1.w*w1.w
                               + a2.x*w2.x + a2.y*w2.y + a2.z*w2.z + a2.w*w2.w;
                }
            }
        }
    }

    float mine = 0.f;
#pragma unroll
    for (int g = 0; g < G; g++)
#pragma unroll
        for (int x = 0; x < S; x++) {
            float v = acc[g][x];
#pragma unroll
            for (int o = 16; o; o >>= 1)
                v += __shfl_xor_sync(0xffffffffu, v, o);
            if (lane == g * S + x) mine = v;
        }

    if (lane < G * S) {
        int g = lane / S, x = lane % S;
        int co = cog * G + g;
        float thr = __ldg(thrp), leak = __ldg(leakp);
        long midx = (((long)b * S + y) * S + x) * COUT + co;
        long oidx = (((long)b * SP + (y + 1)) * SP + (x + 1)) * (long)COUT + co;
        g_buf[out_off + oidx] =
            lif_fire(&g_buf[mem_off + midx], mine, thr, leak);
    }
}

// ---------------- avg-pool 2x2 --------------------------------------------
template<int C, int S, int CI, int CO>   // NCHW(S) -> NCHW(S/2)
__global__ void k_pool_cc(int in_off, int out_off) {
    constexpr int SO = S / 2, RSI = S + 4, ROWSI = S + 2, RSO = SO + 4, ROWSO = SO + 2;
    int idx = blockIdx.x * blockDim.x + threadIdx.x;
    if (idx >= BATCH * C * SO * SO) return;
    int x = idx % SO, y = (idx / SO) % SO;
    int c = (idx / (SO * SO)) % C, b = idx / (SO * SO * C);
    const float* p = g_buf + in_off + ((long)(b * CI + c) * ROWSI + 2 * y + 1) * RSI + 2 * x + 1;
    float v = 0.25f * (p[0] + p[1] + p[RSI] + p[RSI + 1]);
    g_buf[out_off + ((long)(b * CO + c) * ROWSO + y + 1) * RSO + x + 1] = v;
}

template<int C, int S, int CI, int CSTO>  // NCHW(S) -> NHWC(S/2)
__global__ void k_pool_cn(int in_off, int out_off) {
    constexpr int SO = S / 2, RSI = S + 4, ROWSI = S + 2, SPO = SO + 2;
    int idx = blockIdx.x * blockDim.x + threadIdx.x;
    if (idx >= BATCH * C * SO * SO) return;
    int c = idx % C;
    int x = (idx / C) % SO, y = (idx / (C * SO)) % SO, b = idx / (C * SO * SO);
    const float* p = g_buf + in_off + ((long)(b * CI + c) * ROWSI + 2 * y + 1) * RSI + 2 * x + 1;
    float v = 0.25f * (p[0] + p[1] + p[RSI] + p[RSI + 1]);
    g_buf[out_off + (((long)b * SPO + y + 1) * SPO + x + 1) * CSTO + c] = v;
}

template<int C, int S, int CSTI, int CSTO>  // NHWC(S) -> NHWC(S/2)
__global__ void k_pool_nn(int in_off, int out_off) {
    constexpr int SO = S / 2, SPI = S + 2, SPO = SO + 2;
    int idx = blockIdx.x * blockDim.x + threadIdx.x;
    if (idx >= BATCH * C * SO * SO) return;
    int c = idx % C;
    int x = (idx / C) % SO, y = (idx / (C * SO)) % SO, b = idx / (C * SO * SO);
    const float* p = g_buf + in_off + (((long)b * SPI + 2 * y + 1) * SPI + 2 * x + 1) * CSTI + c;
    float v = 0.25f * (p[0] + p[CSTI] + p[(long)SPI * CSTI] + p[(long)(SPI + 1) * CSTI]);
    g_buf[out_off + (((long)b * SPO + y + 1) * SPO + x + 1) * CSTO + c] = v;
}

// ---------------- fully connected: warp per output, 4 batches fused -------
__global__ __launch_bounds__(256)
void k_fc0(const float* __restrict__ W, int mem_off, int out_off,
           const float* __restrict__ thrp, const float* __restrict__ leakp) {
    int gt = blockIdx.x * blockDim.x + threadIdx.x;
    int o = gt >> 5, lane = gt & 31;
    if (o >= 4096) return;
    const float* src = g_buf + OFF_2B;
    float acc[4] = {0.f, 0.f, 0.f, 0.f};
    for (int c = lane; c < 512; c += 32) {
        float4 wv = __ldg((const float4*)(W + (long)o * 2048 + c * 4));
#pragma unroll
        for (int b = 0; b < 4; b++) {
            long base = ((long)(b * 16 + 5)) * 512 + c;
            float a00 = src[base], a01 = src[base + 512];
            float a10 = src[base + 4 * 512], a11 = src[base + 5 * 512];
            acc[b] += wv.x * a00 + wv.y * a01 + wv.z * a10 + wv.w * a11;
        }
    }
#pragma unroll
    for (int b = 0; b < 4; b++)
#pragma unroll
        for (int of = 16; of; of >>= 1)
            acc[b] += __shfl_xor_sync(0xffffffffu, acc[b], of);
    if (lane == 0) {
        float thr = __ldg(thrp), leak = __ldg(leakp);
#pragma unroll
        for (int b = 0; b < 4; b++)
            g_buf[out_off + (long)b * 4096 + o] =
                lif_fire(&g_buf[mem_off + (long)b * 4096 + o], acc[b], thr, leak);
    }
}

template<int KD>
__global__ __launch_bounds__(256)
void k_fc4(const float* __restrict__ W, int in_off, int mem_off, int out_off,
           const float* __restrict__ thrp, const float* __restrict__ leakp,
           int OUTN) {
    int gt = blockIdx.x * blockDim.x + threadIdx.x;
    int o = gt >> 5, lane = gt & 31;
    if (o >= OUTN) return;
    const float4* wp = (const float4*)(W + (long)o * KD);
    const float4* ip = (const float4*)(g_buf + in_off);
    float acc[4] = {0.f, 0.f, 0.f, 0.f};
    for (int k = lane; k < KD / 4; k += 32) {
        float4 wv = __ldg(wp + k);
#pragma unroll
        for (int b = 0; b < 4; b++) {
            float4 a = ip[b * (KD / 4) + k];
            acc[b] += wv.x * a.x + wv.y * a.y + wv.z * a.z + wv.w * a.w;
        }
    }
#pragma unroll
    for (int b = 0; b < 4; b++)
#pragma unroll
        for (int of = 16; of; of >>= 1)
            acc[b] += __shfl_xor_sync(0xffffffffu, acc[b], of);
    if (lane == 0) {
        float thr = __ldg(thrp), leak = __ldg(leakp);
#pragma unroll
        for (int b = 0; b < 4; b++)
            g_buf[out_off + (long)b * OUTN + o] =
                lif_fire(&g_buf[mem_off + (long)b * OUTN + o], acc[b], thr, leak);
    }
}

__global__ void k_logits4(const float* __restrict__ W, int in_off,
                          float* __restrict__ dout) {
    int gt = blockIdx.x * blockDim.x + threadIdx.x;
    int o = gt >> 5, lane = gt & 31;
    if (o >= 10) return;
    const float4* wp = (const float4*)(W + (long)o * 4096);
    const float4* ip = (const float4*)(g_buf + in_off);
    float acc[4] = {0.f, 0.f, 0.f, 0.f};
    for (int k = lane; k < 1024; k += 32) {
        float4 wv = __ldg(wp + k);
#pragma unroll
        for (int b = 0; b < 4; b++) {
            float4 a = ip[b * 1024 + k];
            acc[b] += wv.x * a.x + wv.y * a.y + wv.z * a.z + wv.w * a.w;
        }
    }
#pragma unroll
    for (int b = 0; b < 4; b++)
#pragma unroll
        for (int of = 16; of; of >>= 1)
            acc[b] += __shfl_xor_sync(0xffffffffu, acc[b], of);
    if (lane == 0)
#pragma unroll
        for (int b = 0; b < 4; b++)
            dout[b * 10 + o] += acc[b];
}

// ---------------- launch --------------------------------------------------
static inline int gup(long n, int b) { return (int)((n + b - 1) / b); }

extern "C" void kernel_launch(void* const* d_in, const int* in_sizes, int n_in,
                              void* d_out, int out_size) {
    const float* x = (const float*)d_in[0];
    const float* w[13];
    for (int i = 0; i < 13; i++) w[i] = (const float*)d_in[1 + i];
    const float* fc0w = (const float*)d_in[14];
    const float* fc1w = (const float*)d_in[15];
    const float* fc2w = (const float*)d_in[16];
    const float* thr  = (const float*)d_in[17];
    const float* leak = (const float*)d_in[18];
    float* out = (float*)d_out;

    k_zero<<<gup(TOTAL_BUF, 256), 256>>>(out);
    k_pad_x<<<gup(BATCH * 3 * 1024, 256), 256>>>(x);

    WP wp;
    for (int i = 0; i < 9; i++) wp.p[i] = w[4 + i];
    k_wtrans_all<<<dim3(512, 9), 256>>>(wp);

    for (int t = 0; t < 3; t++) {
        // ---- 32x32, NCHW, TX=4 x TY=2 ----
        k_conv_T<3, 3, 32, 64, 2, 4><<<64 * 2, 256>>>(
            OFF_X, w[0], M0, OFF_32A, thr + 0, leak + 0);
        k_conv_T<64, 64, 32, 64, 2, 4><<<64 * 2, 256>>>(
            OFF_32A, w[1], M1, OFF_32B, thr + 1, leak + 1);
        k_pool_cc<64, 32, 64, 128><<<gup(4L * 64 * 16 * 16, 256), 256>>>(OFF_32B, OFF_16A);

        // ---- 16x16, NCHW, TX=2 x TY=2 ----
        k_conv_T<64, 128, 16, 128, 1, 2><<<128, 256>>>(
            OFF_16A, w[2], M2, OFF_16B, thr + 2, leak + 2);
        k_conv_T<128, 128, 16, 128, 1, 2><<<128, 256>>>(
            OFF_16B, w[3], M3, OFF_16A, thr + 3, leak + 3);
        k_pool_cn<128, 16, 128, 256><<<gup(4L * 128 * 8 * 8, 256), 256>>>(OFF_16A, OFF_8A);

        // ---- 8x8, NHWC, co-blocked (G=4) ----
        k_conv_G<128, 256, 8, 256, 4, 8, 4><<<(256 / 4) * 4, 256>>>(
            OFF_8A, WT4, M4, OFF_8B, thr + 4, leak + 4);
        k_conv_G<256, 256, 8, 256, 4, 8, 4><<<(256 / 4) * 4, 256>>>(
            OFF_8B, WT5, M5, OFF_8A, thr + 5, leak + 5);
        k_conv_G<256, 256, 8, 256, 4, 8, 4><<<(256 / 4) * 4, 256>>>(
            OFF_8A, WT6, M6, OFF_8B, thr + 6, leak + 6);
        k_pool_nn<256, 8, 256, 512><<<gup(4L * 256 * 4 * 4, 256), 256>>>(OFF_8B, OFF_4A);

        // ---- 4x4, NHWC, co-blocked (G=8), rows-resident ----
        k_conv_GR<256, 512, 4, 512, 8, 8, 2><<<(512 / 8) * 2, 256>>>(
            OFF_4A, WT7, M7, OFF_4B, thr + 7, leak + 7);
        k_conv_GR<512, 512, 4, 512, 8, 8, 2><<<(512 / 8) * 2, 256>>>(
            OFF_4B, WT8, M8, OFF_4A, thr + 8, leak + 8);
        k_conv_GR<512, 512, 4, 512, 8, 8, 2><<<(512 / 8) * 2, 256>>>(
            OFF_4A, WT9, M9, OFF_4B, thr + 9, leak + 9);
        k_pool_nn<512, 4, 512, 512><<<gup(4L * 512 * 2 * 2, 256), 256>>>(OFF_4B, OFF_2A);

        // ---- 2x2, NHWC, co-blocked (G=4), rows-resident ----
        k_conv_GR<512, 512, 2, 512, 4, 8, 1><<<(512 / 4) * 1, 256>>>(
            OFF_2A, WT10, M10, OFF_2B, thr + 10, leak + 10);
        k_conv_GR<512, 512, 2, 512, 4, 8, 1><<<(512 / 4) * 1, 256>>>(
            OFF_2B, WT11, M11, OFF_2A, thr + 11, leak + 11);
        k_conv_GR<512, 512, 2, 512, 4, 8, 1><<<(512 / 4) * 1, 256>>>(
            OFF_2A, WT12, M12, OFF_2B, thr + 12, leak + 12);

        // ---- classifier ----
        k_fc0<<<gup(4096L * 32, 256), 256>>>(fc0w, MF0, OFF_FCS0, thr + 13, leak + 13);
        k_fc4<4096><<<gup(4096L * 32, 256), 256>>>(
            fc1w, OFF_FCS0, MF1, OFF_FCS1, thr + 14, leak + 14, 4096);
        k_logits4<<<2, 256>>>(fc2w, OFF_FCS1, out);
    }
}

// round 12
// speedup vs baseline: 1.2053x; 1.2053x over previous
#include <cuda_runtime.h>
#include <cuda_bf16.h>

#define DEV_INLINE __device__ __forceinline__
constexpr int BATCH = 4;
constexpr int NBP = 296;          // persistent grid: 2 blocks per SM
constexpr int NTP = 256;          // threads per block
constexpr int NWP = NBP * 8;      // total warps

// ---------------- buffer layout (floats) ----------------------------------
constexpr int OFF_X    = 0;                         // [4][3][34][36]
constexpr int SZ_X     = BATCH * 3 * 34 * 36;
constexpr int OFF_32A  = OFF_X + SZ_X;              // cap 64
constexpr int SZ_32    = BATCH * 64 * 34 * 36;
constexpr int OFF_32B  = OFF_32A + SZ_32;
constexpr int OFF_16A  = OFF_32B + SZ_32;           // cap 128
constexpr int SZ_16    = BATCH * 128 * 18 * 20;
constexpr int OFF_16B  = OFF_16A + SZ_16;
constexpr int OFF_8A   = OFF_16B + SZ_16;           // NHWC [4][10][10][256]
constexpr int SZ_8     = BATCH * 10 * 10 * 256;
constexpr int OFF_8B   = OFF_8A + SZ_8;
constexpr int OFF_4A   = OFF_8B + SZ_8;             // NHWC [4][6][6][512]
constexpr int SZ_4     = BATCH * 6 * 6 * 512;
constexpr int OFF_4B   = OFF_4A + SZ_4;
constexpr int OFF_2A   = OFF_4B + SZ_4;             // NHWC [4][4][4][512]
constexpr int SZ_2     = BATCH * 4 * 4 * 512;
constexpr int OFF_2B   = OFF_2A + SZ_2;
constexpr int OFF_FCS0 = OFF_2B + SZ_2;             // [4][4096]
constexpr int OFF_FCS1 = OFF_FCS0 + BATCH * 4096;

constexpr int M0  = OFF_FCS1 + BATCH * 4096;
constexpr int M1  = M0  + BATCH * 64  * 32 * 32;
constexpr int M2  = M1  + BATCH * 64  * 32 * 32;
constexpr int M3  = M2  + BATCH * 128 * 16 * 16;
constexpr int M4  = M3  + BATCH * 128 * 16 * 16;
constexpr int M5  = M4  + BATCH * 256 * 8 * 8;
constexpr int M6  = M5  + BATCH * 256 * 8 * 8;
constexpr int M7  = M6  + BATCH * 256 * 8 * 8;
constexpr int M8  = M7  + BATCH * 512 * 4 * 4;
constexpr int M9  = M8  + BATCH * 512 * 4 * 4;
constexpr int M10 = M9  + BATCH * 512 * 4 * 4;
constexpr int M11 = M10 + BATCH * 512 * 2 * 2;
constexpr int M12 = M11 + BATCH * 512 * 2 * 2;
constexpr int MF0 = M12 + BATCH * 512 * 2 * 2;
constexpr int MF1 = MF0 + BATCH * 4096;
constexpr int TOTAL_BUF = MF1 + BATCH * 4096;

__device__ __align__(16) float g_buf[TOTAL_BUF];

// transposed weights [co][tap][ci] for conv layers 4..12
constexpr long WT4  = 0;
constexpr long WT5  = WT4  + 256L * 128 * 9;
constexpr long WT6  = WT5  + 256L * 256 * 9;
constexpr long WT7  = WT6  + 256L * 256 * 9;
constexpr long WT8  = WT7  + 512L * 256 * 9;
constexpr long WT9  = WT8  + 512L * 512 * 9;
constexpr long WT10 = WT9  + 512L * 512 * 9;
constexpr long WT11 = WT10 + 512L * 512 * 9;
constexpr long WT12 = WT11 + 512L * 512 * 9;
constexpr long WT_TOTAL = WT12 + 512L * 512 * 9;
__device__ __align__(16) float g_wt[WT_TOTAL];

// ---------------- grid barrier: atomic arrive, volatile-load spin ---------
__device__ unsigned g_cnt = 0;
__device__ unsigned g_rel = 0;

DEV_INLINE void gsync(unsigned e) {
    __syncthreads();
    if (threadIdx.x == 0) {
        __threadfence();
        unsigned v = atomicAdd(&g_cnt, 1u);
        if (v + 1u == e * (unsigned)NBP) {
            __threadfence();
            *(volatile unsigned*)&g_rel = e;
        } else {
            while (*(volatile unsigned*)&g_rel < e) { }
        }
        __threadfence();
    }
    __syncthreads();
}

// ---------------- multi-compartment LIF (K=2), exact ----------------------
DEV_INLINE float lif_fire(float* memp, float syn, float thr, float leak) {
    float m = leak * (*memp) + syn;
    float e0 = m / thr          - 1.0f;
    float o0 = 1.0f - m / (2.0f * thr);
    float e1 = m / (2.0f * thr) - 1.0f;
    float o1 = 1.0f - m / (4.0f * thr);
    float v = 0.0f;
    if (e0 > 0.0f && o0 >= 0.0f) v = 1.0f;
    if (e1 > 0.0f && o1 >= 0.0f) v = 2.0f;
    *memp = m - thr * v;
    return v;
}

// ---------------- pre-kernels ---------------------------------------------
__global__ void k_zero(float* __restrict__ dout) {
    int i = blockIdx.x * blockDim.x + threadIdx.x;
    if (i < TOTAL_BUF) g_buf[i] = 0.0f;
    if (i < BATCH * 10) dout[i] = 0.0f;
}

__global__ void k_pad_x(const float* __restrict__ x) {
    int idx = blockIdx.x * blockDim.x + threadIdx.x;
    if (idx >= BATCH * 3 * 32 * 32) return;
    int xx = idx & 31;
    int y  = (idx >> 5) & 31;
    int c  = (idx >> 10) % 3;
    int b  = idx / (3 * 1024);
    g_buf[OFF_X + ((b * 3 + c) * 34 + (y + 1)) * 36 + (xx + 1)] = x[idx];
}

struct WP { const float* p[9]; };
__global__ void k_wtrans_all(WP wp) {
    __shared__ float s[4608];
    const int CINs[9]  = {128, 256, 256, 256, 512, 512, 512, 512, 512};
    const int COUTs[9] = {256, 256, 256, 512, 512, 512, 512, 512, 512};
    const long OFFs[9] = {WT4, WT5, WT6, WT7, WT8, WT9, WT10, WT11, WT12};
    int l  = blockIdx.y;
    int co = blockIdx.x;
    int CIN = CINs[l];
    if (co >= COUTs[l]) return;
    const float* src = wp.p[l] + (long)co * CIN * 9;
    float* dst = g_wt + OFFs[l] + (long)co * CIN * 9;
    int n = CIN * 9;
    for (int i = threadIdx.x; i < n; i += 256) s[i] = src[i];
    __syncthreads();
    for (int i = threadIdx.x; i < n; i += 256) {
        int ci = i % CIN, t = i / CIN;
        dst[i] = s[ci * 9 + t];
    }
}

// ---------------- persistent layer bodies (R9 kernels, job-stride) --------
// conv flavor T: NCHW, job = (co, part), smem weights, thread does TX cols.
template<int CIN, int CICAP, int S, int COUT, int PARTS, int TX>
DEV_INLINE void convT_p(int in_off, const float* __restrict__ w,
                        int mem_off, int out_off,
                        const float* __restrict__ thrp,
                        const float* __restrict__ leakp, float* sw) {
    constexpr int RS = S + 4, ROWS = S + 2, NX = S / TX;
    constexpr int PLANE = ROWS * RS;
    constexpr int P = BATCH * S * NX;
    constexpr int TPJ = P / PARTS;
    static_assert(TPJ == 256, "block must exactly cover its partition");
    float thr = __ldg(thrp), leak = __ldg(leakp);

    for (int jobi = blockIdx.x; jobi < COUT * PARTS; jobi += NBP) {
        int co = jobi / PARTS, part = jobi % PARTS;
        __syncthreads();
        for (int i = threadIdx.x; i < CIN * 9; i += 256)
            sw[(i / 9) * 12 + (i % 9)] = __ldg(w + (long)co * CIN * 9 + i);
        __syncthreads();

        int tid = part * TPJ + threadIdx.x;
        int x0 = (tid % NX) * TX;
        int y  = (tid / NX) % S;
        int b  = tid / (NX * S);

        const float* ip = g_buf + in_off + (long)b * CICAP * PLANE + y * RS + x0;
        float accA[TX], accB[TX];
#pragma unroll
        for (int t = 0; t < TX; t++) { accA[t] = 0.f; accB[t] = 0.f; }

        for (int ci = 0; ci < CIN; ci++) {
            const float* p = ip + ci * PLANE;
            float r[3][TX + 2];
#pragma unroll
            for (int rr = 0; rr < 3; rr++) {
                if constexpr (TX == 4) {
                    float4 a = __ldg((const float4*)(p + rr * RS));
                    float4 c = __ldg((const float4*)(p + rr * RS + 4));
                    r[rr][0] = a.x; r[rr][1] = a.y; r[rr][2] = a.z; r[rr][3] = a.w;
                    r[rr][4] = c.x; r[rr][5] = c.y;
                } else {
                    float2 a = __ldg((const float2*)(p + rr * RS));
                    float2 c = __ldg((const float2*)(p + rr * RS + 2));
                    r[rr][0] = a.x; r[rr][1] = a.y; r[rr][2] = c.x; r[rr][3] = c.y;
                }
            }
            float4 wa = *(const float4*)(sw + ci * 12);
            float4 wb = *(const float4*)(sw + ci * 12 + 4);
            float4 wc = *(const float4*)(sw + ci * 12 + 8);
            float wv[9] = {wa.x, wa.y, wa.z, wa.w, wb.x, wb.y, wb.z, wb.w, wc.x};
#pragma unroll
            for (int t = 0; t < TX; t++) {
                accA[t] += wv[0]*r[0][t] + wv[2]*r[0][t+2] + wv[4]*r[1][t+1]
                         + wv[6]*r[2][t] + wv[8]*r[2][t+2];
                accB[t] += wv[1]*r[0][t+1] + wv[3]*r[1][t] + wv[5]*r[1][t+2]
                         + wv[7]*r[2][t+1];
            }
        }

        long mbase = (((long)b * COUT + co) * S + y) * S + x0;
        long obase = (((long)b * COUT + co) * ROWS + (y + 1)) * RS + (x0 + 1);
#pragma unroll
        for (int t = 0; t < TX; t++)
            g_buf[out_off + obase + t] =
                lif_fire(&g_buf[mem_off + mbase + t], accA[t] + accB[t], thr, leak);
    }
}

// conv flavor G: NHWC, job = (cog, part), warp = (b, y), G co's per warp.
template<int CIN, int CST, int S, int COUT, int G, int WPB, int PARTS>
DEV_INLINE void convG_p(int in_off, long wt_off, int mem_off, int out_off,
                        const float* __restrict__ thrp,
                        const float* __restrict__ leakp, float* sw) {
    constexpr int SP = S + 2;
    constexpr int CHUNKS = CIN / 128;
    static_assert(WPB * PARTS == BATCH * S, "warps must exactly cover jobs");
    static_assert(WPB == 8, "8 warps per block");
    static_assert(G * S <= 32, "one lane per output");
    int warp = threadIdx.x >> 5, lane = threadIdx.x & 31;
    float thr = __ldg(thrp), leak = __ldg(leakp);
    int cb = lane * 4;

    for (int jobi = blockIdx.x; jobi < (COUT / G) * PARTS; jobi += NBP) {
        int cog  = jobi / PARTS;
        int part = jobi % PARTS;
        int job  = part * WPB + warp;
        int b = job / S, y = job % S;

        float acc[G][S];
#pragma unroll
        for (int g = 0; g < G; g++)
#pragma unroll
            for (int x = 0; x < S; x++) acc[g][x] = 0.f;

        for (int ch = 0; ch < CHUNKS; ch++) {
            __syncthreads();
            const float* wsrc = g_wt + wt_off + ((long)cog * G) * CIN * 9 + ch * 128;
            for (int i = threadIdx.x; i < G * 9 * 32; i += 256) {
                int g = i / (9 * 32);
                int r = i % (9 * 32);
                int t = r / 32, c4 = r % 32;
                *(float4*)(sw + (g * 9 + t) * 128 + c4 * 4) =
                    __ldg((const float4*)(wsrc + ((long)g * 9 + t) * CIN + c4 * 4));
            }
            __syncthreads();

            const float* base = g_buf + in_off + ch * 128 + cb;
#pragma unroll
            for (int rr = 0; rr < 3; rr++) {
                const float* rp = base + ((long)(b * SP + y + rr) * SP) * CST;
                float4 a[S + 2];
#pragma unroll
                for (int j = 0; j < S + 2; j++)
                    a[j] = __ldg((const float4*)(rp + (long)j * CST));
#pragma unroll
                for (int g = 0; g < G; g++) {
                    const float* wrow = sw + (g * 9 + rr * 3) * 128 + cb;
                    float4 w0 = *(const float4*)(wrow);
                    float4 w1 = *(const float4*)(wrow + 128);
                    float4 w2 = *(const float4*)(wrow + 256);
#pragma unroll
                    for (int x = 0; x < S; x++) {
                        float4 a0 = a[x], a1 = a[x + 1], a2 = a[x + 2];
                        acc[g][x] += a0.x*w0.x + a0.y*w0.y + a0.z*w0.z + a0.w*w0.w
                                   + a1.x*w1.x + a1.y*w1.y + a1.z*w1.z + a1.w*w1.w
                                   + a2.x*w2.x + a2.y*w2.y + a2.z*w2.z + a2.w*w2.w;
                    }
                }
            }
        }

        float mine = 0.f;
#pragma unroll
        for (int g = 0; g < G; g++)
#pragma unroll
            for (int x = 0; x < S; x++) {
                float v = acc[g][x];
#pragma unroll
                for (int o = 16; o; o >>= 1)
                    v += __shfl_xor_sync(0xffffffffu, v, o);
                if (lane == g * S + x) mine = v;
            }

        if (lane < G * S) {
            int g = lane / S, x = lane % S;
            int co = cog * G + g;
            long midx = (((long)b * S + y) * S + x) * COUT + co;
            long oidx = (((long)b * SP + (y + 1)) * SP + (x + 1)) * (long)COUT + co;
            g_buf[out_off + oidx] =
                lif_fire(&g_buf[mem_off + midx], mine, thr, leak);
        }
    }
}

// pools (grid-stride)
template<int C, int S, int CI, int CO>   // NCHW(S) -> NCHW(S/2)
DEV_INLINE void pool_cc_p(int in_off, int out_off) {
    constexpr int SO = S / 2, RSI = S + 4, ROWSI = S + 2, RSO = SO + 4, ROWSO = SO + 2;
    for (int idx = blockIdx.x * NTP + threadIdx.x; idx < BATCH * C * SO * SO; idx += NBP * NTP) {
        int x = idx % SO, y = (idx / SO) % SO;
        int c = (idx / (SO * SO)) % C, b = idx / (SO * SO * C);
        const float* p = g_buf + in_off + ((long)(b * CI + c) * ROWSI + 2 * y + 1) * RSI + 2 * x + 1;
        float v = 0.25f * (p[0] + p[1] + p[RSI] + p[RSI + 1]);
        g_buf[out_off + ((long)(b * CO + c) * ROWSO + y + 1) * RSO + x + 1] = v;
    }
}

template<int C, int S, int CI, int CSTO>  // NCHW(S) -> NHWC(S/2)
DEV_INLINE void pool_cn_p(int in_off, int out_off) {
    constexpr int SO = S / 2, RSI = S + 4, ROWSI = S + 2, SPO = SO + 2;
    for (int idx = blockIdx.x * NTP + threadIdx.x; idx < BATCH * C * SO * SO; idx += NBP * NTP) {
        int c = idx % C;
        int x = (idx / C) % SO, y = (idx / (C * SO)) % SO, b = idx / (C * SO * SO);
        const float* p = g_buf + in_off + ((long)(b * CI + c) * ROWSI + 2 * y + 1) * RSI + 2 * x + 1;
        float v = 0.25f * (p[0] + p[1] + p[RSI] + p[RSI + 1]);
        g_buf[out_off + (((long)b * SPO + y + 1) * SPO + x + 1) * CSTO + c] = v;
    }
}

template<int C, int S, int CSTI, int CSTO>  // NHWC(S) -> NHWC(S/2)
DEV_INLINE void pool_nn_p(int in_off, int out_off) {
    constexpr int SO = S / 2, SPI = S + 2, SPO = SO + 2;
    for (int idx = blockIdx.x * NTP + threadIdx.x; idx < BATCH * C * SO * SO; idx += NBP * NTP) {
        int c = idx % C;
        int x = (idx / C) % SO, y = (idx / (C * SO)) % SO, b = idx / (C * SO * SO);
        const float* p = g_buf + in_off + (((long)b * SPI + 2 * y + 1) * SPI + 2 * x + 1) * CSTI + c;
        float v = 0.25f * (p[0] + p[CSTI] + p[(long)SPI * CSTI] + p[(long)(SPI + 1) * CSTI]);
        g_buf[out_off + (((long)b * SPO + y + 1) * SPO + x + 1) * CSTO + c] = v;
    }
}

// fc0: reads NHWC padded [4][4][4][512]; flat f = c*4 + y*2 + x
DEV_INLINE void fc0_p(const float* __restrict__ W, int mem_off, int out_off,
                      const float* __restrict__ thrp, const float* __restrict__ leakp) {
    int lane = threadIdx.x & 31;
    int wg0 = blockIdx.x * 8 + (threadIdx.x >> 5);
    float thr = __ldg(thrp), leak = __ldg(leakp);
    const float* src = g_buf + OFF_2B;
    for (int o = wg0; o < 4096; o += NWP) {
        float acc[4] = {0.f, 0.f, 0.f, 0.f};
        for (int c = lane; c < 512; c += 32) {
            float4 wv = __ldg((const float4*)(W + (long)o * 2048 + c * 4));
#pragma unroll
            for (int b = 0; b < 4; b++) {
                long base = ((long)(b * 16 + 5)) * 512 + c;
                float a00 = src[base], a01 = src[base + 512];
                float a10 = src[base + 4 * 512], a11 = src[base + 5 * 512];
                acc[b] += wv.x * a00 + wv.y * a01 + wv.z * a10 + wv.w * a11;
            }
        }
#pragma unroll
        for (int b = 0; b < 4; b++)
#pragma unroll
            for (int of = 16; of; of >>= 1)
                acc[b] += __shfl_xor_sync(0xffffffffu, acc[b], of);
        if (lane == 0)
#pragma unroll
            for (int b = 0; b < 4; b++)
                g_buf[out_off + (long)b * 4096 + o] =
                    lif_fire(&g_buf[mem_off + (long)b * 4096 + o], acc[b], thr, leak);
    }
}

template<int KD>
DEV_INLINE void fc4_p(const float* __restrict__ W, int in_off, int mem_off, int out_off,
                      const float* __restrict__ thrp, const float* __restrict__ leakp,
                      int OUTN) {
    int lane = threadIdx.x & 31;
    int wg0 = blockIdx.x * 8 + (threadIdx.x >> 5);
    float thr = __ldg(thrp), leak = __ldg(leakp);
    const float4* ip = (const float4*)(g_buf + in_off);
    for (int o = wg0; o < OUTN; o += NWP) {
        const float4* wp = (const float4*)(W + (long)o * KD);
        float acc[4] = {0.f, 0.f, 0.f, 0.f};
        for (int k = lane; k < KD / 4; k += 32) {
            float4 wv = __ldg(wp + k);
#pragma unroll
            for (int b = 0; b < 4; b++) {
                float4 a = ip[b * (KD / 4) + k];
                acc[b] += wv.x * a.x + wv.y * a.y + wv.z * a.z + wv.w * a.w;
            }
        }
#pragma unroll
        for (int b = 0; b < 4; b++)
#pragma unroll
            for (int of = 16; of; of >>= 1)
                acc[b] += __shfl_xor_sync(0xffffffffu, acc[b], of);
        if (lane == 0)
#pragma unroll
            for (int b = 0; b < 4; b++)
                g_buf[out_off + (long)b * OUTN + o] =
                    lif_fire(&g_buf[mem_off + (long)b * OUTN + o], acc[b], thr, leak);
    }
}

DEV_INLINE void logits_p(const float* __restrict__ W, int in_off,
                         float* __restrict__ dout) {
    int lane = threadIdx.x & 31;
    int wg0 = blockIdx.x * 8 + (threadIdx.x >> 5);
    const float4* ip = (const float4*)(g_buf + in_off);
    for (int o = wg0; o < 10; o += NWP) {
        const float4* wp = (const float4*)(W + (long)o * 4096);
        float acc[4] = {0.f, 0.f, 0.f, 0.f};
        for (int k = lane; k < 1024; k += 32) {
            float4 wv = __ldg(wp + k);
#pragma unroll
            for (int b = 0; b < 4; b++) {
                float4 a = ip[b * 1024 + k];
                acc[b] += wv.x * a.x + wv.y * a.y + wv.z * a.z + wv.w * a.w;
            }
        }
#pragma unroll
        for (int b = 0; b < 4; b++)
#pragma unroll
            for (int of = 16; of; of >>= 1)
                acc[b] += __shfl_xor_sync(0xffffffffu, acc[b], of);
        if (lane == 0)
#pragma unroll
            for (int b = 0; b < 4; b++)
                dout[b * 10 + o] += acc[b];
    }
}

// ---------------- the persistent network kernel ---------------------------
struct NetArgs {
    const float* w0; const float* w1; const float* w2; const float* w3;
    const float* fc0w; const float* fc1w; const float* fc2w;
    const float* thr; const float* leak;
    float* out;
};

__global__ void __launch_bounds__(NTP, 2) k_net(NetArgs a) {
    __shared__ __align__(16) float sw[4608];   // max: G=4 conv_G = 18.4 KB
    __shared__ unsigned s_base;
    if (threadIdx.x == 0) s_base = *(volatile unsigned*)&g_rel;
    __syncthreads();
    unsigned e = s_base;

    for (int t = 0; t < 3; t++) {
        convT_p<3, 3, 32, 64, 4, 4>(OFF_X, a.w0, M0, OFF_32A, a.thr + 0, a.leak + 0, sw);
        gsync(++e);
        convT_p<64, 64, 32, 64, 4, 4>(OFF_32A, a.w1, M1, OFF_32B, a.thr + 1, a.leak + 1, sw);
        gsync(++e);
        pool_cc_p<64, 32, 64, 128>(OFF_32B, OFF_16A);
        gsync(++e);
        convT_p<64, 128, 16, 128, 2, 2>(OFF_16A, a.w2, M2, OFF_16B, a.thr + 2, a.leak + 2, sw);
        gsync(++e);
        convT_p<128, 128, 16, 128, 2, 2>(OFF_16B, a.w3, M3, OFF_16A, a.thr + 3, a.leak + 3, sw);
        gsync(++e);
        pool_cn_p<128, 16, 128, 256>(OFF_16A, OFF_8A);
        gsync(++e);
        convG_p<128, 256, 8, 256, 2, 8, 4>(OFF_8A, WT4, M4, OFF_8B, a.thr + 4, a.leak + 4, sw);
        gsync(++e);
        convG_p<256, 256, 8, 256, 2, 8, 4>(OFF_8B, WT5, M5, OFF_8A, a.thr + 5, a.leak + 5, sw);
        gsync(++e);
        convG_p<256, 256, 8, 256, 2, 8, 4>(OFF_8A, WT6, M6, OFF_8B, a.thr + 6, a.leak + 6, sw);
        gsync(++e);
        pool_nn_p<256, 8, 256, 512>(OFF_8B, OFF_4A);
        gsync(++e);
        convG_p<256, 512, 4, 512, 4, 8, 2>(OFF_4A, WT7, M7, OFF_4B, a.thr + 7, a.leak + 7, sw);
        gsync(++e);
        convG_p<512, 512, 4, 512, 4, 8, 2>(OFF_4B, WT8, M8, OFF_4A, a.thr + 8, a.leak + 8, sw);
        gsync(++e);
        convG_p<512, 512, 4, 512, 4, 8, 2>(OFF_4A, WT9, M9, OFF_4B, a.thr + 9, a.leak + 9, sw);
        gsync(++e);
        pool_nn_p<512, 4, 512, 512>(OFF_4B, OFF_2A);
        gsync(++e);
        convG_p<512, 512, 2, 512, 2, 8, 1>(OFF_2A, WT10, M10, OFF_2B, a.thr + 10, a.leak + 10, sw);
        gsync(++e);
        convG_p<512, 512, 2, 512, 2, 8, 1>(OFF_2B, WT11, M11, OFF_2A, a.thr + 11, a.leak + 11, sw);
        gsync(++e);
        convG_p<512, 512, 2, 512, 2, 8, 1>(OFF_2A, WT12, M12, OFF_2B, a.thr + 12, a.leak + 12, sw);
        gsync(++e);
        fc0_p(a.fc0w, MF0, OFF_FCS0, a.thr + 13, a.leak + 13);
        gsync(++e);
        fc4_p<4096>(a.fc1w, OFF_FCS0, MF1, OFF_FCS1, a.thr + 14, a.leak + 14, 4096);
        gsync(++e);
        logits_p(a.fc2w, OFF_FCS1, a.out);
        // no barrier needed before next step's conv0: it touches only
        // OFF_32A / M0, which nothing after the last barrier reads.
    }
}

// ---------------- launch --------------------------------------------------
static inline int gup(long n, int b) { return (int)((n + b - 1) / b); }

extern "C" void kernel_launch(void* const* d_in, const int* in_sizes, int n_in,
                              void* d_out, int out_size) {
    const float* x = (const float*)d_in[0];
    const float* w[13];
    for (int i = 0; i < 13; i++) w[i] = (const float*)d_in[1 + i];
    const float* fc0w = (const float*)d_in[14];
    const float* fc1w = (const float*)d_in[15];
    const float* fc2w = (const float*)d_in[16];
    const float* thr  = (const float*)d_in[17];
    const float* leak = (const float*)d_in[18];
    float* out = (float*)d_out;

    k_zero<<<gup(TOTAL_BUF, 256), 256>>>(out);
    k_pad_x<<<gup(BATCH * 3 * 1024, 256), 256>>>(x);

    WP wp;
    for (int i = 0; i < 9; i++) wp.p[i] = w[4 + i];
    k_wtrans_all<<<dim3(512, 9), 256>>>(wp);

    NetArgs a;
    a.w0 = w[0]; a.w1 = w[1]; a.w2 = w[2]; a.w3 = w[3];
    a.fc0w = fc0w; a.fc1w = fc1w; a.fc2w = fc2w;
    a.thr = thr; a.leak = leak; a.out = out;
    k_net<<<NBP, NTP>>>(a);
}

// round 13
// speedup vs baseline: 1.2606x; 1.0459x over previous
#include <cuda_runtime.h>
#include <cuda_bf16.h>

#define DEV_INLINE __device__ __forceinline__
constexpr int BATCH = 4;
constexpr int NBP = 296;          // persistent grid: 2 blocks per SM
constexpr int NTP = 256;          // threads per block
constexpr int NWP = NBP * 8;      // total warps

// ---------------- buffer layout (floats): all activations NHWC padded -----
constexpr int OFF_X    = 0;                                    // [4][34][34][4]
constexpr int OFF_32A  = OFF_X   + BATCH * 34 * 34 * 4;        // [4][34][34][64]
constexpr int OFF_32B  = OFF_32A + BATCH * 34 * 34 * 64;
constexpr int OFF_16A  = OFF_32B + BATCH * 34 * 34 * 64;       // [4][18][18][64]
constexpr int OFF_16B  = OFF_16A + BATCH * 18 * 18 * 64;       // [4][18][18][128]
constexpr int OFF_16C  = OFF_16B + BATCH * 18 * 18 * 128;
constexpr int OFF_8A   = OFF_16C + BATCH * 18 * 18 * 128;      // [4][10][10][128]
constexpr int OFF_8B   = OFF_8A  + BATCH * 10 * 10 * 128;      // [4][10][10][256]
constexpr int OFF_8C   = OFF_8B  + BATCH * 10 * 10 * 256;
constexpr int OFF_4A   = OFF_8C  + BATCH * 10 * 10 * 256;      // [4][6][6][256]
constexpr int OFF_4B   = OFF_4A  + BATCH * 6 * 6 * 256;        // [4][6][6][512]
constexpr int OFF_4C   = OFF_4B  + BATCH * 6 * 6 * 512;
constexpr int OFF_2A   = OFF_4C  + BATCH * 6 * 6 * 512;        // [4][4][4][512]
constexpr int OFF_2B   = OFF_2A  + BATCH * 4 * 4 * 512;
constexpr int OFF_FCS0 = OFF_2B  + BATCH * 4 * 4 * 512;        // [4][4096]
constexpr int OFF_FCS1 = OFF_FCS0 + BATCH * 4096;

// membranes: NHWC dense
constexpr int M0  = OFF_FCS1 + BATCH * 4096;
constexpr int M1  = M0  + BATCH * 32 * 32 * 64;
constexpr int M2  = M1  + BATCH * 32 * 32 * 64;
constexpr int M3  = M2  + BATCH * 16 * 16 * 128;
constexpr int M4  = M3  + BATCH * 16 * 16 * 128;
constexpr int M5  = M4  + BATCH * 8 * 8 * 256;
constexpr int M6  = M5  + BATCH * 8 * 8 * 256;
constexpr int M7  = M6  + BATCH * 8 * 8 * 256;
constexpr int M8  = M7  + BATCH * 4 * 4 * 512;
constexpr int M9  = M8  + BATCH * 4 * 4 * 512;
constexpr int M10 = M9  + BATCH * 4 * 4 * 512;
constexpr int M11 = M10 + BATCH * 2 * 2 * 512;
constexpr int M12 = M11 + BATCH * 2 * 2 * 512;
constexpr int MF0 = M12 + BATCH * 2 * 2 * 512;
constexpr int MF1 = MF0 + BATCH * 4096;
constexpr int TOTAL_BUF = MF1 + BATCH * 4096;

__device__ __align__(16) float g_buf[TOTAL_BUF];

// transposed weights [co][tap][ci] for conv layers 1..12
constexpr long WT1  = 0;
constexpr long WT2  = WT1  + 64L  * 64  * 9;
constexpr long WT3  = WT2  + 128L * 64  * 9;
constexpr long WT4  = WT3  + 128L * 128 * 9;
constexpr long WT5  = WT4  + 256L * 128 * 9;
constexpr long WT6  = WT5  + 256L * 256 * 9;
constexpr long WT7  = WT6  + 256L * 256 * 9;
constexpr long WT8  = WT7  + 512L * 256 * 9;
constexpr long WT9  = WT8  + 512L * 512 * 9;
constexpr long WT10 = WT9  + 512L * 512 * 9;
constexpr long WT11 = WT10 + 512L * 512 * 9;
constexpr long WT12 = WT11 + 512L * 512 * 9;
constexpr long WT_TOTAL = WT12 + 512L * 512 * 9;
__device__ __align__(16) float g_wt[WT_TOTAL];

// ---------------- grid barrier: atomic arrive, volatile-load spin ---------
__device__ unsigned g_cnt = 0;
__device__ unsigned g_rel = 0;

DEV_INLINE void gsync(unsigned e) {
    __syncthreads();
    if (threadIdx.x == 0) {
        __threadfence();
        unsigned v = atomicAdd(&g_cnt, 1u);
        if (v + 1u == e * (unsigned)NBP) {
            __threadfence();
            *(volatile unsigned*)&g_rel = e;
        } else {
            while (*(volatile unsigned*)&g_rel < e) { }
        }
        __threadfence();
    }
    __syncthreads();
}

// ---------------- multi-compartment LIF (K=2), exact ----------------------
DEV_INLINE float lif_fire(float* memp, float syn, float thr, float leak) {
    float m = leak * (*memp) + syn;
    float e0 = m / thr          - 1.0f;
    float o0 = 1.0f - m / (2.0f * thr);
    float e1 = m / (2.0f * thr) - 1.0f;
    float o1 = 1.0f - m / (4.0f * thr);
    float v = 0.0f;
    if (e0 > 0.0f && o0 >= 0.0f) v = 1.0f;
    if (e1 > 0.0f && o1 >= 0.0f) v = 2.0f;
    *memp = m - thr * v;
    return v;
}

// ---------------- pre-kernels ---------------------------------------------
__global__ void k_zero(float* __restrict__ dout) {
    int i = blockIdx.x * blockDim.x + threadIdx.x;
    if (i < TOTAL_BUF) g_buf[i] = 0.0f;
    if (i < BATCH * 10) dout[i] = 0.0f;
}

__global__ void k_pad_x(const float* __restrict__ x) {
    int idx = blockIdx.x * blockDim.x + threadIdx.x;
    if (idx >= BATCH * 3 * 32 * 32) return;
    int xx = idx & 31;
    int y  = (idx >> 5) & 31;
    int c  = (idx >> 10) % 3;
    int b  = idx / (3 * 1024);
    g_buf[OFF_X + (((b * 34) + y + 1) * 34 + (xx + 1)) * 4 + c] = x[idx];
}

struct WP { const float* p[12]; };
__global__ void k_wtrans_all(WP wp) {
    __shared__ float s[4608];
    const int CINs[12]  = {64, 64, 128, 128, 256, 256, 256, 512, 512, 512, 512, 512};
    const int COUTs[12] = {64, 128, 128, 256, 256, 256, 512, 512, 512, 512, 512, 512};
    const long OFFs[12] = {WT1, WT2, WT3, WT4, WT5, WT6, WT7, WT8, WT9, WT10, WT11, WT12};
    int l  = blockIdx.y;
    int co = blockIdx.x;
    int CIN = CINs[l];
    if (co >= COUTs[l]) return;
    const float* src = wp.p[l] + (long)co * CIN * 9;
    float* dst = g_wt + OFFs[l] + (long)co * CIN * 9;
    int n = CIN * 9;
    for (int i = threadIdx.x; i < n; i += 256) s[i] = src[i];
    __syncthreads();
    for (int i = threadIdx.x; i < n; i += 256) {
        int ci = i % CIN, t = i / CIN;
        dst[i] = s[ci * 9 + t];
    }
}

// ---------------- layer 0: CIN=3, warp per pixel, lanes = co --------------
DEV_INLINE void convL0_p(const float* __restrict__ w0,
                         const float* __restrict__ thrp,
                         const float* __restrict__ leakp, float* sw) {
    // stage weights transposed: sw[t*64 + co], t = ci*9 + ky*3 + kx
    __syncthreads();
    for (int i = threadIdx.x; i < 64 * 27; i += NTP) {
        int co = i / 27, t = i % 27;
        sw[t * 64 + co] = __ldg(w0 + co * 27 + t);
    }
    __syncthreads();
    int warp = threadIdx.x >> 5, lane = threadIdx.x & 31;
    float thr = __ldg(thrp), leak = __ldg(leakp);
    for (int pj = blockIdx.x * 8 + warp; pj < BATCH * 32 * 32; pj += NBP * 8) {
        int x = pj & 31, y = (pj >> 5) & 31, b = pj >> 10;
        const float* ip = g_buf + OFF_X + (((long)(b * 34) + y) * 34 + x) * 4;
        float iv[27];
#pragma unroll
        for (int dy = 0; dy < 3; dy++)
#pragma unroll
            for (int dx = 0; dx < 3; dx++)
#pragma unroll
                for (int ci = 0; ci < 3; ci++)
                    iv[ci * 9 + dy * 3 + dx] = __ldg(ip + (dy * 34 + dx) * 4 + ci);
        float a0 = 0.f, a1 = 0.f;
#pragma unroll
        for (int t = 0; t < 27; t++) {
            a0 += sw[t * 64 + lane] * iv[t];
            a1 += sw[t * 64 + 32 + lane] * iv[t];
        }
        long o = (((long)(b * 34) + y + 1) * 34 + (x + 1)) * 64;
        long m = (((long)(b * 32) + y) * 32 + x) * 64;
        g_buf[OFF_32A + o + lane] =
            lif_fire(&g_buf[M0 + m + lane], a0, thr, leak);
        g_buf[OFF_32A + o + 32 + lane] =
            lif_fire(&g_buf[M0 + m + 32 + lane], a1, thr, leak);
    }
}

// ---------------- convS: NHWC streaming, warp=(b,y), G co's, CPL ch/lane --
template<int CIN, int CST, int S, int COUT, int G, int CPL>
DEV_INLINE void convS_p(int in_off, long wt_off, int mem_off, int out_off,
                        const float* __restrict__ thrp,
                        const float* __restrict__ leakp, float* sw) {
    constexpr int SP = S + 2;
    constexpr int CH = 32 * CPL;
    constexpr int CHUNKS = CIN / CH;
    constexpr int PARTS = BATCH * S / 8;
    constexpr int NJOBS = (COUT / G) * PARTS;
    static_assert(G * S <= 32, "one lane per output");
    int warp = threadIdx.x >> 5, lane = threadIdx.x & 31;
    float thr = __ldg(thrp), leak = __ldg(leakp);

    for (int jobi = blockIdx.x; jobi < NJOBS; jobi += NBP) {
        int cog  = jobi / PARTS;
        int part = jobi % PARTS;
        int wj = part * 8 + warp;
        int b = wj / S, y = wj % S;

        float acc[G][S];
#pragma unroll
        for (int g = 0; g < G; g++)
#pragma unroll
            for (int x = 0; x < S; x++) acc[g][x] = 0.f;

        for (int ch = 0; ch < CHUNKS; ch++) {
            __syncthreads();
            const float* wsrc = g_wt + wt_off + ((long)cog * G) * CIN * 9 + ch * CH;
            for (int i = threadIdx.x; i < G * 9 * CH; i += NTP) {
                int g = i / (9 * CH);
                int r = i % (9 * CH);
                int t = r / CH, c = r % CH;
                sw[(g * 9 + t) * CH + c] = __ldg(wsrc + ((long)g * 9 + t) * CIN + c);
            }
            __syncthreads();

            const float* base = g_buf + in_off + ch * CH + lane * CPL;
#pragma unroll
            for (int rr = 0; rr < 3; rr++) {
                float wv[G][3][CPL];
#pragma unroll
                for (int g = 0; g < G; g++)
#pragma unroll
                    for (int dx = 0; dx < 3; dx++)
#pragma unroll
                        for (int c = 0; c < CPL; c++)
                            wv[g][dx][c] = sw[(g * 9 + rr * 3 + dx) * CH + lane * CPL + c];
                const float* rp = base + ((long)(b * SP + y + rr) * SP) * CST;
#pragma unroll
                for (int j = 0; j < SP; j++) {
                    float a[CPL];
                    if constexpr (CPL == 2) {
                        float2 v = __ldg((const float2*)(rp + (long)j * CST));
                        a[0] = v.x; a[1] = v.y;
                    } else {
                        float4 v = __ldg((const float4*)(rp + (long)j * CST));
                        a[0] = v.x; a[1] = v.y; a[2] = v.z; a[3] = v.w;
                    }
#pragma unroll
                    for (int g = 0; g < G; g++)
#pragma unroll
                        for (int dx = 0; dx < 3; dx++) {
                            int t = j - dx;
                            if (t >= 0 && t < S) {
#pragma unroll
                                for (int c = 0; c < CPL; c++)
                                    acc[g][t] += wv[g][dx][c] * a[c];
                            }
                        }
                }
            }
        }

        float mine = 0.f;
#pragma unroll
        for (int g = 0; g < G; g++)
#pragma unroll
            for (int x = 0; x < S; x++) {
                float v = acc[g][x];
#pragma unroll
                for (int o = 16; o; o >>= 1)
                    v += __shfl_xor_sync(0xffffffffu, v, o);
                if (lane == g * S + x) mine = v;
            }
        if (lane < G * S) {
            int g = lane / S, x = lane % S;
            int co = cog * G + g;
            long midx = (((long)b * S + y) * S + x) * COUT + co;
            long oidx = (((long)b * SP + (y + 1)) * SP + (x + 1)) * (long)COUT + co;
            g_buf[out_off + oidx] =
                lif_fire(&g_buf[mem_off + midx], mine, thr, leak);
        }
    }
}

// ---------------- convG: NHWC array-form (S<=8), proven in R9/R12 ---------
template<int CIN, int CST, int S, int COUT, int G, int WPB, int PARTS>
DEV_INLINE void convG_p(int in_off, long wt_off, int mem_off, int out_off,
                        const float* __restrict__ thrp,
                        const float* __restrict__ leakp, float* sw) {
    constexpr int SP = S + 2;
    constexpr int CHUNKS = CIN / 128;
    static_assert(WPB * PARTS == BATCH * S, "warps must exactly cover jobs");
    static_assert(WPB == 8, "8 warps per block");
    static_assert(G * S <= 32, "one lane per output");
    int warp = threadIdx.x >> 5, lane = threadIdx.x & 31;
    float thr = __ldg(thrp), leak = __ldg(leakp);
    int cb = lane * 4;

    for (int jobi = blockIdx.x; jobi < (COUT / G) * PARTS; jobi += NBP) {
        int cog  = jobi / PARTS;
        int part = jobi % PARTS;
        int job  = part * WPB + warp;
        int b = job / S, y = job % S;

        float acc[G][S];
#pragma unroll
        for (int g = 0; g < G; g++)
#pragma unroll
            for (int x = 0; x < S; x++) acc[g][x] = 0.f;

        for (int ch = 0; ch < CHUNKS; ch++) {
            __syncthreads();
            const float* wsrc = g_wt + wt_off + ((long)cog * G) * CIN * 9 + ch * 128;
            for (int i = threadIdx.x; i < G * 9 * 32; i += 256) {
                int g = i / (9 * 32);
                int r = i % (9 * 32);
                int t = r / 32, c4 = r % 32;
                *(float4*)(sw + (g * 9 + t) * 128 + c4 * 4) =
                    __ldg((const float4*)(wsrc + ((long)g * 9 + t) * CIN + c4 * 4));
            }
            __syncthreads();

            const float* base = g_buf + in_off + ch * 128 + cb;
#pragma unroll
            for (int rr = 0; rr < 3; rr++) {
                const float* rp = base + ((long)(b * SP + y + rr) * SP) * CST;
                float4 a[S + 2];
#pragma unroll
                for (int j = 0; j < S + 2; j++)
                    a[j] = __ldg((const float4*)(rp + (long)j * CST));
#pragma unroll
                for (int g = 0; g < G; g++) {
                    const float* wrow = sw + (g * 9 + rr * 3) * 128 + cb;
                    float4 w0 = *(const float4*)(wrow);
                    float4 w1 = *(const float4*)(wrow + 128);
                    float4 w2 = *(const float4*)(wrow + 256);
#pragma unroll
                    for (int x = 0; x < S; x++) {
                        float4 a0 = a[x], a1 = a[x + 1], a2 = a[x + 2];
                        acc[g][x] += a0.x*w0.x + a0.y*w0.y + a0.z*w0.z + a0.w*w0.w
                                   + a1.x*w1.x + a1.y*w1.y + a1.z*w1.z + a1.w*w1.w
                                   + a2.x*w2.x + a2.y*w2.y + a2.z*w2.z + a2.w*w2.w;
                    }
                }
            }
        }

        float mine = 0.f;
#pragma unroll
        for (int g = 0; g < G; g++)
#pragma unroll
            for (int x = 0; x < S; x++) {
                float v = acc[g][x];
#pragma unroll
                for (int o = 16; o; o >>= 1)
                    v += __shfl_xor_sync(0xffffffffu, v, o);
                if (lane == g * S + x) mine = v;
            }

        if (lane < G * S) {
            int g = lane / S, x = lane % S;
            int co = cog * G + g;
            long midx = (((long)b * S + y) * S + x) * COUT + co;
            long oidx = (((long)b * SP + (y + 1)) * SP + (x + 1)) * (long)COUT + co;
            g_buf[out_off + oidx] =
                lif_fire(&g_buf[mem_off + midx], mine, thr, leak);
        }
    }
}

// ---------------- pool (NHWC -> NHWC) -------------------------------------
template<int C, int S, int CSTI, int CSTO>
DEV_INLINE void pool_nn_p(int in_off, int out_off) {
    constexpr int SO = S / 2, SPI = S + 2, SPO = SO + 2;
    for (int idx = blockIdx.x * NTP + threadIdx.x; idx < BATCH * C * SO * SO; idx += NBP * NTP) {
        int c = idx % C;
        int x = (idx / C) % SO, y = (idx / (C * SO)) % SO, b = idx / (C * SO * SO);
        const float* p = g_buf + in_off + (((long)b * SPI + 2 * y + 1) * SPI + 2 * x + 1) * CSTI + c;
        float v = 0.25f * (p[0] + p[CSTI] + p[(long)SPI * CSTI] + p[(long)(SPI + 1) * CSTI]);
        g_buf[out_off + (((long)b * SPO + y + 1) * SPO + x + 1) * CSTO + c] = v;
    }
}

// ---------------- fully connected (unchanged from R11) --------------------
DEV_INLINE void fc0_p(const float* __restrict__ W, int mem_off, int out_off,
                      const float* __restrict__ thrp, const float* __restrict__ leakp) {
    int lane = threadIdx.x & 31;
    int wg0 = blockIdx.x * 8 + (threadIdx.x >> 5);
    float thr = __ldg(thrp), leak = __ldg(leakp);
    const float* src = g_buf + OFF_2B;
    for (int o = wg0; o < 4096; o += NWP) {
        float acc[4] = {0.f, 0.f, 0.f, 0.f};
        for (int c = lane; c < 512; c += 32) {
            float4 wv = __ldg((const float4*)(W + (long)o * 2048 + c * 4));
#pragma unroll
            for (int b = 0; b < 4; b++) {
                long base = ((long)(b * 16 + 5)) * 512 + c;
                float a00 = src[base], a01 = src[base + 512];
                float a10 = src[base + 4 * 512], a11 = src[base + 5 * 512];
                acc[b] += wv.x * a00 + wv.y * a01 + wv.z * a10 + wv.w * a11;
            }
        }
#pragma unroll
        for (int b = 0; b < 4; b++)
#pragma unroll
            for (int of = 16; of; of >>= 1)
                acc[b] += __shfl_xor_sync(0xffffffffu, acc[b], of);
        if (lane == 0)
#pragma unroll
            for (int b = 0; b < 4; b++)
                g_buf[out_off + (long)b * 4096 + o] =
                    lif_fire(&g_buf[mem_off + (long)b * 4096 + o], acc[b], thr, leak);
    }
}

template<int KD>
DEV_INLINE void fc4_p(const float* __restrict__ W, int in_off, int mem_off, int out_off,
                      const float* __restrict__ thrp, const float* __restrict__ leakp,
                      int OUTN) {
    int lane = threadIdx.x & 31;
    int wg0 = blockIdx.x * 8 + (threadIdx.x >> 5);
    float thr = __ldg(thrp), leak = __ldg(leakp);
    const float4* ip = (const float4*)(g_buf + in_off);
    for (int o = wg0; o < OUTN; o += NWP) {
        const float4* wp = (const float4*)(W + (long)o * KD);
        float acc[4] = {0.f, 0.f, 0.f, 0.f};
        for (int k = lane; k < KD / 4; k += 32) {
            float4 wv = __ldg(wp + k);
#pragma unroll
            for (int b = 0; b < 4; b++) {
                float4 a = ip[b * (KD / 4) + k];
                acc[b] += wv.x * a.x + wv.y * a.y + wv.z * a.z + wv.w * a.w;
            }
        }
#pragma unroll
        for (int b = 0; b < 4; b++)
#pragma unroll
            for (int of = 16; of; of >>= 1)
                acc[b] += __shfl_xor_sync(0xffffffffu, acc[b], of);
        if (lane == 0)
#pragma unroll
            for (int b = 0; b < 4; b++)
                g_buf[out_off + (long)b * OUTN + o] =
                    lif_fire(&g_buf[mem_off + (long)b * OUTN + o], acc[b], thr, leak);
    }
}

DEV_INLINE void logits_p(const float* __restrict__ W, int in_off,
                         float* __restrict__ dout) {
    int lane = threadIdx.x & 31;
    int wg0 = blockIdx.x * 8 + (threadIdx.x >> 5);
    const float4* ip = (const float4*)(g_buf + in_off);
    for (int o = wg0; o < 10; o += NWP) {
        const float4* wp = (const float4*)(W + (long)o * 4096);
        float acc[4] = {0.f, 0.f, 0.f, 0.f};
        for (int k = lane; k < 1024; k += 32) {
            float4 wv = __ldg(wp + k);
#pragma unroll
            for (int b = 0; b < 4; b++) {
                float4 a = ip[b * 1024 + k];
                acc[b] += wv.x * a.x + wv.y * a.y + wv.z * a.z + wv.w * a.w;
            }
        }
#pragma unroll
        for (int b = 0; b < 4; b++)
#pragma unroll
            for (int of = 16; of; of >>= 1)
                acc[b] += __shfl_xor_sync(0xffffffffu, acc[b], of);
        if (lane == 0)
#pragma unroll
            for (int b = 0; b < 4; b++)
                dout[b * 10 + o] += acc[b];
    }
}

// ---------------- the persistent network kernel ---------------------------
struct NetArgs {
    const float* w0;
    const float* fc0w; const float* fc1w; const float* fc2w;
    const float* thr; const float* leak;
    float* out;
};

__global__ void __launch_bounds__(NTP, 2) k_net(NetArgs a) {
    __shared__ __align__(16) float sw[4608];
    __shared__ unsigned s_base;
    if (threadIdx.x == 0) s_base = *(volatile unsigned*)&g_rel;
    __syncthreads();
    unsigned e = s_base;

    for (int t = 0; t < 3; t++) {
        convL0_p(a.w0, a.thr + 0, a.leak + 0, sw);
        gsync(++e);
        convS_p<64, 64, 32, 64, 1, 2>(OFF_32A, WT1, M1, OFF_32B, a.thr + 1, a.leak + 1, sw);
        gsync(++e);
        pool_nn_p<64, 32, 64, 64>(OFF_32B, OFF_16A);
        gsync(++e);
        convS_p<64, 64, 16, 128, 2, 2>(OFF_16A, WT2, M2, OFF_16B, a.thr + 2, a.leak + 2, sw);
        gsync(++e);
        convS_p<128, 128, 16, 128, 2, 4>(OFF_16B, WT3, M3, OFF_16C, a.thr + 3, a.leak + 3, sw);
        gsync(++e);
        pool_nn_p<128, 16, 128, 128>(OFF_16C, OFF_8A);
        gsync(++e);
        convG_p<128, 128, 8, 256, 2, 8, 4>(OFF_8A, WT4, M4, OFF_8B, a.thr + 4, a.leak + 4, sw);
        gsync(++e);
        convG_p<256, 256, 8, 256, 2, 8, 4>(OFF_8B, WT5, M5, OFF_8C, a.thr + 5, a.leak + 5, sw);
        gsync(++e);
        convG_p<256, 256, 8, 256, 2, 8, 4>(OFF_8C, WT6, M6, OFF_8B, a.thr + 6, a.leak + 6, sw);
        gsync(++e);
        pool_nn_p<256, 8, 256, 256>(OFF_8B, OFF_4A);
        gsync(++e);
        convG_p<256, 256, 4, 512, 4, 8, 2>(OFF_4A, WT7, M7, OFF_4B, a.thr + 7, a.leak + 7, sw);
        gsync(++e);
        convG_p<512, 512, 4, 512, 4, 8, 2>(OFF_4B, WT8, M8, OFF_4C, a.thr + 8, a.leak + 8, sw);
        gsync(++e);
        convG_p<512, 512, 4, 512, 4, 8, 2>(OFF_4C, WT9, M9, OFF_4B, a.thr + 9, a.leak + 9, sw);
        gsync(++e);
        pool_nn_p<512, 4, 512, 512>(OFF_4B, OFF_2A);
        gsync(++e);
        convG_p<512, 512, 2, 512, 2, 8, 1>(OFF_2A, WT10, M10, OFF_2B, a.thr + 10, a.leak + 10, sw);
        gsync(++e);
        convG_p<512, 512, 2, 512, 2, 8, 1>(OFF_2B, WT11, M11, OFF_2A, a.thr + 11, a.leak + 11, sw);
        gsync(++e);
        convG_p<512, 512, 2, 512, 2, 8, 1>(OFF_2A, WT12, M12, OFF_2B, a.thr + 12, a.leak + 12, sw);
        gsync(++e);
        fc0_p(a.fc0w, MF0, OFF_FCS0, a.thr + 13, a.leak + 13);
        gsync(++e);
        fc4_p<4096>(a.fc1w, OFF_FCS0, MF1, OFF_FCS1, a.thr + 14, a.leak + 14, 4096);
        gsync(++e);
        logits_p(a.fc2w, OFF_FCS1, a.out);
        // next-step L0 touches only OFF_32A/M0 (guarded by its own staging
        // syncthreads + the gsync after it); logits reads FCS1 — disjoint.
    }
}

// ---------------- launch --------------------------------------------------
static inline int gup(long n, int b) { return (int)((n + b - 1) / b); }

extern "C" void kernel_launch(void* const* d_in, const int* in_sizes, int n_in,
                              void* d_out, int out_size) {
    const float* x = (const float*)d_in[0];
    const float* w[13];
    for (int i = 0; i < 13; i++) w[i] = (const float*)d_in[1 + i];
    const float* fc0w = (const float*)d_in[14];
    const float* fc1w = (const float*)d_in[15];
    const float* fc2w = (const float*)d_in[16];
    const float* thr  = (const float*)d_in[17];
    const float* leak = (const float*)d_in[18];
    float* out = (float*)d_out;

    k_zero<<<gup(TOTAL_BUF, 256), 256>>>(out);
    k_pad_x<<<gup(BATCH * 3 * 1024, 256), 256>>>(x);

    WP wp;
    for (int i = 0; i < 12; i++) wp.p[i] = w[1 + i];
    k_wtrans_all<<<dim3(512, 12), 256>>>(wp);

    NetArgs a;
    a.w0 = w[0];
    a.fc0w = fc0w; a.fc1w = fc1w; a.fc2w = fc2w;
    a.thr = thr; a.leak = leak; a.out = out;
    k_net<<<NBP, NTP>>>(a);
}